// round 14
// baseline (speedup 1.0000x reference)
#include <cuda_runtime.h>
#include <cuda_bf16.h>
#include <math.h>
#include <stdint.h>

#define DM   768
#define DI   1536
#define DS   16
#define DTR  48
#define NL   4
#define VOC  32000
#define BB   2
#define LL   1024
#define BL   (BB*LL)      // 2048
#define XDW  (DTR + 2*DS) // 80

// ---------------- fp32 scratch ----------------
__device__ float g_x    [BL*DM];
__device__ float g_xr   [BL*2*DI];
__device__ float g_xin  [BL*DI];
__device__ float g_xdbl [BL*XDW];
__device__ float g_delta[BL*DI];
__device__ float g_xp   [8*BL*XDW];   // x_proj split-K partials
__device__ float g_op   [3*BL*DM];    // out_proj split-K partials

// ---------------- bf16 hi/lo split scratch -------------
__device__ __align__(16) __nv_bfloat16 g_Emb_h [VOC*DM];
__device__ __align__(16) __nv_bfloat16 g_Emb_l [VOC*DM];
__device__ __align__(16) __nv_bfloat16 g_Win_h [NL*2*DI*DM];
__device__ __align__(16) __nv_bfloat16 g_Win_l [NL*2*DI*DM];
__device__ __align__(16) __nv_bfloat16 g_Wout_h[NL*DM*DI];
__device__ __align__(16) __nv_bfloat16 g_Wout_l[NL*DM*DI];
__device__ __align__(16) __nv_bfloat16 g_Wx_h  [NL*128*DI];
__device__ __align__(16) __nv_bfloat16 g_Wx_l  [NL*128*DI];
__device__ __align__(16) __nv_bfloat16 g_Wdt_h [NL*DI*64];
__device__ __align__(16) __nv_bfloat16 g_Wdt_l [NL*DI*64];
__device__ __align__(16) __nv_bfloat16 g_Xn_h  [BL*DM];
__device__ __align__(16) __nv_bfloat16 g_Xn_l  [BL*DM];
__device__ __align__(16) __nv_bfloat16 g_Xin_h [BL*DI];
__device__ __align__(16) __nv_bfloat16 g_Xin_l [BL*DI];
__device__ __align__(16) __nv_bfloat16 g_Xd_h  [BL*64];
__device__ __align__(16) __nv_bfloat16 g_Xd_l  [BL*64];
__device__ __align__(16) __nv_bfloat16 g_Y_h   [BL*DI];
__device__ __align__(16) __nv_bfloat16 g_Y_l   [BL*DI];

// ================= common device helpers =================
__device__ __forceinline__ uint32_t smem_u32(const void* p) {
    uint32_t a;
    asm("{ .reg .u64 t; cvta.to.shared.u64 t, %1; cvt.u32.u64 %0, t; }" : "=r"(a) : "l"(p));
    return a;
}
__device__ __forceinline__ void mma16816(float* c, const uint32_t* a, const uint32_t* b) {
    asm volatile(
        "mma.sync.aligned.m16n8k16.row.col.f32.bf16.bf16.f32 "
        "{%0,%1,%2,%3}, {%4,%5,%6,%7}, {%8,%9}, {%0,%1,%2,%3};"
        : "+f"(c[0]), "+f"(c[1]), "+f"(c[2]), "+f"(c[3])
        : "r"(a[0]), "r"(a[1]), "r"(a[2]), "r"(a[3]), "r"(b[0]), "r"(b[1]));
}
#define CPA16(dst, src) \
    asm volatile("cp.async.cg.shared.global [%0], [%1], 16;" :: "r"(dst), "l"(src) : "memory")
#define CPA_COMMIT() asm volatile("cp.async.commit_group;" ::: "memory")
#define CPA_WAIT(n)  asm volatile("cp.async.wait_group %0;" :: "n"(n) : "memory")
#define LDSM4(r, addr) \
    asm volatile("ldmatrix.sync.aligned.m8n8.x4.shared.b16 {%0,%1,%2,%3}, [%4];" \
        : "=r"((r)[0]), "=r"((r)[1]), "=r"((r)[2]), "=r"((r)[3]) : "r"(addr))

__device__ __forceinline__ float softplusf(float v) {
    return (v > 0.f) ? v + log1pf(expf(-v)) : log1pf(expf(v));
}

// ================= split: fp32 -> bf16 hi/lo, padded row-major =============
__global__ void split_kernel(const float* __restrict__ src, int lda, int M, int K,
                             __nv_bfloat16* __restrict__ dhi,
                             __nv_bfloat16* __restrict__ dlo, int Mp, int Kp) {
    int idx = blockIdx.x * blockDim.x + threadIdx.x;
    int nkg = Kp >> 3;
    if (idx >= Mp * nkg) return;
    int r = idx / nkg;
    int k0 = (idx % nkg) << 3;
    __align__(16) __nv_bfloat16 hi[8], lo[8];
    #pragma unroll
    for (int j = 0; j < 8; j++) {
        int k = k0 + j;
        float v = (r < M && k < K) ? src[(size_t)r * lda + k] : 0.f;
        __nv_bfloat16 h = __float2bfloat16_rn(v);
        hi[j] = h;
        lo[j] = __float2bfloat16_rn(v - __bfloat162float(h));
    }
    size_t o = (size_t)r * Kp + k0;
    *(uint4*)(dhi + o) = *(const uint4*)hi;
    *(uint4*)(dlo + o) = *(const uint4*)lo;
}

// ================= gemm256: 128x256 tile, ldmatrix, cp.async 2-stage ========
// MODE: 0 = store, 2 = softplus(acc + bias[col])
#define SROW  40
#define MATA  (128*SROW)     // 5120 elems
#define MATB  (256*SROW)     // 10240 elems
#define STG_E (2*MATA + 2*MATB)   // 30720 elems per stage

template<int MODE>
__global__ __launch_bounds__(256, 1) void gemm256(const __nv_bfloat16* __restrict__ Ah_,
                                                  const __nv_bfloat16* __restrict__ Al_,
                                                  const __nv_bfloat16* __restrict__ Bh_,
                                                  const __nv_bfloat16* __restrict__ Bl_,
                                                  float* __restrict__ C, int ldc,
                                                  int Kp, int KT, size_t zstride,
                                                  const float* __restrict__ bias) {
    extern __shared__ __nv_bfloat16 sm[];
    uint32_t smb = smem_u32(sm);
    int tid = threadIdx.x;
    int m0 = blockIdx.y * 128, n0 = blockIdx.x * 256;
    int kbase = blockIdx.z * (KT * 32);
    C += (size_t)blockIdx.z * zstride;

    int lr = tid >> 2;            // 0..63
    int lk = (tid & 3) * 8;       // 0,8,16,24

    int lane = tid & 31;
    int w = tid >> 5;
    int wm = (w & 1) * 64;
    int wn = (w >> 1) * 64;
    int g = lane >> 2;
    int tig = lane & 3;

    // ldmatrix per-lane byte offsets (within a stage)
    uint32_t a_off = 2u * ((wm + (lane & 15)) * SROW + (lane >> 4) * 8);
    uint32_t b_off = 2u * ((wn + ((lane & 7) | ((lane >> 1) & 8))) * SROW
                           + ((lane >> 3) & 1) * 8);

    float acc[4][8][4];
    #pragma unroll
    for (int i = 0; i < 4; i++)
        #pragma unroll
        for (int j = 0; j < 8; j++)
            #pragma unroll
            for (int r = 0; r < 4; r++) acc[i][j][r] = 0.f;

    auto load_stage = [&](int kt, int s) {
        int k0 = kbase + kt * 32;
        uint32_t sbase = smb + 2u * (s * STG_E);
        #pragma unroll
        for (int h = 0; h < 2; h++) {
            int row = lr + 64 * h;
            size_t off = (size_t)(m0 + row) * Kp + k0 + lk;
            uint32_t d = sbase + 2u * (row * SROW + lk);
            CPA16(d,             Ah_ + off);
            CPA16(d + 2 * MATA,  Al_ + off);
        }
        #pragma unroll
        for (int h = 0; h < 4; h++) {
            int row = lr + 64 * h;
            size_t off = (size_t)(n0 + row) * Kp + k0 + lk;
            uint32_t d = sbase + 2u * (2 * MATA + row * SROW + lk);
            CPA16(d,             Bh_ + off);
            CPA16(d + 2 * MATB,  Bl_ + off);
        }
        CPA_COMMIT();
    };

    auto compute_stage = [&](int s) {
        uint32_t sbase = smb + 2u * (s * STG_E);
        #pragma unroll
        for (int ks = 0; ks < 2; ks++) {
            uint32_t abase = sbase + a_off + 2u * (ks * 16);
            uint32_t bbase = sbase + 2u * (2 * MATA) + b_off + 2u * (ks * 16);
            uint32_t fah[16], fbh[16], flo[16];
            #pragma unroll
            for (int mt = 0; mt < 4; mt++) LDSM4(&fah[mt * 4], abase + 2u * (mt * 16 * SROW));
            #pragma unroll
            for (int p = 0; p < 4; p++)  LDSM4(&fbh[p * 4], bbase + 2u * (p * 16 * SROW));
            #pragma unroll
            for (int mt = 0; mt < 4; mt++)
                #pragma unroll
                for (int nt = 0; nt < 8; nt++)
                    mma16816(acc[mt][nt], &fah[mt * 4], &fbh[(nt >> 1) * 4 + (nt & 1) * 2]);
            // A_lo pass
            #pragma unroll
            for (int mt = 0; mt < 4; mt++) LDSM4(&flo[mt * 4], abase + 2u * MATA + 2u * (mt * 16 * SROW));
            #pragma unroll
            for (int mt = 0; mt < 4; mt++)
                #pragma unroll
                for (int nt = 0; nt < 8; nt++)
                    mma16816(acc[mt][nt], &flo[mt * 4], &fbh[(nt >> 1) * 4 + (nt & 1) * 2]);
            // B_lo pass
            #pragma unroll
            for (int p = 0; p < 4; p++)  LDSM4(&flo[p * 4], bbase + 2u * MATB + 2u * (p * 16 * SROW));
            #pragma unroll
            for (int mt = 0; mt < 4; mt++)
                #pragma unroll
                for (int nt = 0; nt < 8; nt++)
                    mma16816(acc[mt][nt], &fah[mt * 4], &flo[(nt >> 1) * 4 + (nt & 1) * 2]);
        }
    };

    load_stage(0, 0);
    for (int kt = 0; kt < KT; kt++) {
        int s = kt & 1;
        if (kt + 1 < KT) { load_stage(kt + 1, s ^ 1); CPA_WAIT(1); }
        else             { CPA_WAIT(0); }
        __syncthreads();
        compute_stage(s);
        __syncthreads();
    }

    // epilogue (all N multiples of 256 -> no guards)
    #pragma unroll
    for (int mt = 0; mt < 4; mt++) {
        #pragma unroll
        for (int nt = 0; nt < 8; nt++) {
            int r = m0 + wm + mt * 16 + g;
            int c = n0 + wn + nt * 8 + 2 * tig;
            float* p0 = C + (size_t)r * ldc + c;
            float* p1 = C + (size_t)(r + 8) * ldc + c;
            float v0 = acc[mt][nt][0], v1 = acc[mt][nt][1];
            float v2 = acc[mt][nt][2], v3 = acc[mt][nt][3];
            if (MODE == 2) {
                float b0 = bias[c], b1 = bias[c + 1];
                v0 = softplusf(v0 + b0); v1 = softplusf(v1 + b1);
                v2 = softplusf(v2 + b0); v3 = softplusf(v3 + b1);
            }
            p0[0] = v0; p0[1] = v1;
            p1[0] = v2; p1[1] = v3;
        }
    }
}

// ================= gemm128: 128x128 tile (x_proj, split-K) =================
__global__ __launch_bounds__(256) void gemm128(const __nv_bfloat16* __restrict__ Ah_,
                                               const __nv_bfloat16* __restrict__ Al_,
                                               const __nv_bfloat16* __restrict__ Bh_,
                                               const __nv_bfloat16* __restrict__ Bl_,
                                               float* __restrict__ C, int ldc,
                                               int N, int Kp, int KT, size_t zstride) {
    extern __shared__ __nv_bfloat16 sm[];
    uint32_t smb = smem_u32(sm);
    int tid = threadIdx.x;
    int m0 = blockIdx.y * 128, n0 = blockIdx.x * 128;
    int kbase = blockIdx.z * (KT * 32);
    C += (size_t)blockIdx.z * zstride;

    int lrow = tid >> 2;
    int lkc = (tid & 3) * 8;
    int lane = tid & 31;
    int w = tid >> 5;
    int wm = (w & 1) * 64;
    int wn = (w >> 1) * 32;
    int g = lane >> 2;
    int tig = lane & 3;

    uint32_t a_off = 2u * ((wm + (lane & 15)) * SROW + (lane >> 4) * 8);
    uint32_t b_off = 2u * ((wn + ((lane & 7) | ((lane >> 1) & 8))) * SROW
                           + ((lane >> 3) & 1) * 8);

    float acc[4][4][4];
    #pragma unroll
    for (int i = 0; i < 4; i++)
        #pragma unroll
        for (int j = 0; j < 4; j++)
            #pragma unroll
            for (int r = 0; r < 4; r++) acc[i][j][r] = 0.f;

    auto load_stage = [&](int kt, int s) {
        int k0 = kbase + kt * 32;
        #pragma unroll
        for (int h = 0; h < 2; h++) {
            int row = lrow + 64 * h;
            size_t aoff = (size_t)(m0 + row) * Kp + k0 + lkc;
            size_t boff = (size_t)(n0 + row) * Kp + k0 + lkc;
            uint32_t sb = smb + (uint32_t)((s * 4 * MATA + row * SROW + lkc) * 2);
            CPA16(sb,                Ah_ + aoff);
            CPA16(sb + MATA * 2,     Al_ + aoff);
            CPA16(sb + 2 * MATA * 2, Bh_ + boff);
            CPA16(sb + 3 * MATA * 2, Bl_ + boff);
        }
        CPA_COMMIT();
    };

    auto compute_stage = [&](int s) {
        uint32_t sbase = smb + 2u * (s * 4 * MATA);
        #pragma unroll
        for (int ks = 0; ks < 2; ks++) {
            uint32_t abase = sbase + a_off + 2u * (ks * 16);
            uint32_t bbase = sbase + 2u * (2 * MATA) + b_off + 2u * (ks * 16);
            uint32_t fah[16], fbh[8], flo[16];
            #pragma unroll
            for (int mt = 0; mt < 4; mt++) LDSM4(&fah[mt * 4], abase + 2u * (mt * 16 * SROW));
            #pragma unroll
            for (int p = 0; p < 2; p++)  LDSM4(&fbh[p * 4], bbase + 2u * (p * 16 * SROW));
            #pragma unroll
            for (int mt = 0; mt < 4; mt++)
                #pragma unroll
                for (int nt = 0; nt < 4; nt++)
                    mma16816(acc[mt][nt], &fah[mt * 4], &fbh[(nt >> 1) * 4 + (nt & 1) * 2]);
            #pragma unroll
            for (int mt = 0; mt < 4; mt++) LDSM4(&flo[mt * 4], abase + 2u * MATA + 2u * (mt * 16 * SROW));
            #pragma unroll
            for (int mt = 0; mt < 4; mt++)
                #pragma unroll
                for (int nt = 0; nt < 4; nt++)
                    mma16816(acc[mt][nt], &flo[mt * 4], &fbh[(nt >> 1) * 4 + (nt & 1) * 2]);
            #pragma unroll
            for (int p = 0; p < 2; p++)  LDSM4(&flo[p * 4], bbase + 2u * MATA + 2u * (p * 16 * SROW));
            #pragma unroll
            for (int mt = 0; mt < 4; mt++)
                #pragma unroll
                for (int nt = 0; nt < 4; nt++)
                    mma16816(acc[mt][nt], &fah[mt * 4], &flo[(nt >> 1) * 4 + (nt & 1) * 2]);
        }
    };

    load_stage(0, 0);
    for (int kt = 0; kt < KT; kt++) {
        int s = kt & 1;
        if (kt + 1 < KT) { load_stage(kt + 1, s ^ 1); CPA_WAIT(1); }
        else             { CPA_WAIT(0); }
        __syncthreads();
        compute_stage(s);
        __syncthreads();
    }

    #pragma unroll
    for (int mt = 0; mt < 4; mt++) {
        #pragma unroll
        for (int nt = 0; nt < 4; nt++) {
            int r = m0 + wm + mt * 16 + g;
            int c = n0 + wn + nt * 8 + 2 * tig;
            if (c < N) {
                float* p0 = C + (size_t)r * ldc + c;
                float* p1 = C + (size_t)(r + 8) * ldc + c;
                p0[0] = acc[mt][nt][0]; p1[0] = acc[mt][nt][2];
                if (c + 1 < N) { p0[1] = acc[mt][nt][1]; p1[1] = acc[mt][nt][3]; }
            }
        }
    }
}

// ================= reduces =================
__global__ void xreduce_kernel(const float* __restrict__ xp, float* __restrict__ xdbl,
                               __nv_bfloat16* __restrict__ xdh, __nv_bfloat16* __restrict__ xdl) {
    int i = blockIdx.x * blockDim.x + threadIdx.x;
    if (i >= BL * XDW) return;
    float s = 0.f;
    #pragma unroll
    for (int z = 0; z < 8; z++) s += xp[(size_t)z * BL * XDW + i];
    xdbl[i] = s;
    int c = i % XDW, r = i / XDW;
    if (c < 64) {
        __nv_bfloat16 h = __float2bfloat16_rn(s);
        xdh[(size_t)r * 64 + c] = h;
        xdl[(size_t)r * 64 + c] = __float2bfloat16_rn(s - __bfloat162float(h));
    }
}
__global__ void oreduce_kernel(const float* __restrict__ p, float* __restrict__ x) {
    int i = blockIdx.x * blockDim.x + threadIdx.x;
    if (i >= BL * DM) return;
    x[i] += p[i] + p[(size_t)BL * DM + i] + p[(size_t)2 * BL * DM + i];
}

// ================= elementwise =================
__global__ void embed_kernel(const int* __restrict__ ids, const float* __restrict__ emb,
                             float* __restrict__ x) {
    int i = blockIdx.x * blockDim.x + threadIdx.x;
    if (i >= BL * DM) return;
    int r = i / DM, c = i % DM;
    x[i] = emb[(size_t)ids[r] * DM + c];
}

__global__ __launch_bounds__(256) void rmsnorm_split_kernel(const float* __restrict__ x,
                                                            const float* __restrict__ w,
                                                            __nv_bfloat16* __restrict__ oh,
                                                            __nv_bfloat16* __restrict__ ol) {
    int row = blockIdx.x;
    const float* xrow = x + (size_t)row * DM;
    float s = 0.f;
    for (int c = threadIdx.x; c < DM; c += 256) { float v = xrow[c]; s = fmaf(v, v, s); }
    #pragma unroll
    for (int off = 16; off; off >>= 1) s += __shfl_xor_sync(0xffffffffu, s, off);
    __shared__ float red[8];
    if ((threadIdx.x & 31) == 0) red[threadIdx.x >> 5] = s;
    __syncthreads();
    float tot = red[0] + red[1] + red[2] + red[3] + red[4] + red[5] + red[6] + red[7];
    float sc = rsqrtf(tot * (1.0f / DM) + 1e-5f);
    for (int c = threadIdx.x; c < DM; c += 256) {
        float v = xrow[c] * sc * w[c];
        __nv_bfloat16 h = __float2bfloat16_rn(v);
        oh[(size_t)row * DM + c] = h;
        ol[(size_t)row * DM + c] = __float2bfloat16_rn(v - __bfloat162float(h));
    }
}

__global__ void conv_silu_split_kernel(const float* __restrict__ xr, const float* __restrict__ cw,
                                       const float* __restrict__ cb, float* __restrict__ xin,
                                       __nv_bfloat16* __restrict__ xih, __nv_bfloat16* __restrict__ xil) {
    int i = blockIdx.x * blockDim.x + threadIdx.x;
    if (i >= BL * DI) return;
    int d = i % DI;
    int bl = i / DI;
    int l = bl % LL;
    float w0 = cw[d * 4], w1 = cw[d * 4 + 1], w2 = cw[d * 4 + 2], w3 = cw[d * 4 + 3];
    const float* base = xr + (size_t)bl * (2 * DI) + d;
    float acc = cb[d];
    if (l >= 3) acc = fmaf(w0, base[-3 * (2 * DI)], acc);
    if (l >= 2) acc = fmaf(w1, base[-2 * (2 * DI)], acc);
    if (l >= 1) acc = fmaf(w2, base[-1 * (2 * DI)], acc);
    acc = fmaf(w3, base[0], acc);
    float v = acc / (1.f + expf(-acc));
    xin[i] = v;
    __nv_bfloat16 h = __float2bfloat16_rn(v);
    xih[i] = h;
    xil[i] = __float2bfloat16_rn(v - __bfloat162float(h));
}

// ---------------- selective scan + fused gate + bf16 split ----------------
__global__ __launch_bounds__(128) void scan_gate_kernel(const float* __restrict__ u,
                                                        const float* __restrict__ delta,
                                                        const float* __restrict__ xdbl,
                                                        const float* __restrict__ A_log,
                                                        const float* __restrict__ Dp,
                                                        const float* __restrict__ xr,
                                                        __nv_bfloat16* __restrict__ yh,
                                                        __nv_bfloat16* __restrict__ yl) {
    int tid = blockIdx.x * blockDim.x + threadIdx.x;
    if (tid >= BB * DI * 2) return;
    int half = tid & 1;
    int pair = tid >> 1;
    int d = pair % DI;
    int b = pair / DI;

    float A[8];
    float A0 = -expf(A_log[d * DS]);
    bool structured = true;
    #pragma unroll
    for (int n = 0; n < 8; n++) {
        int ng = half * 8 + n;
        A[n] = -expf(A_log[d * DS + ng]);
        float e = (float)(ng + 1) * A0;
        if (fabsf(A[n] - e) > 1e-3f * fabsf(e)) structured = false;
    }
    float Dd = Dp[d];
    float h[8];
    #pragma unroll
    for (int n = 0; n < 8; n++) h[n] = 0.f;

    const float* up = u + (size_t)b * LL * DI + d;
    const float* dp = delta + (size_t)b * LL * DI + d;
    const float* xp = xdbl + (size_t)b * LL * XDW + DTR + half * 8;
    const float* rp = xr + (size_t)b * LL * (2 * DI) + DI + d;
    size_t ybase = (size_t)b * LL * DI + d;

    float del = dp[0], uu = up[0], rr = rp[0];
    float4 B0 = *(const float4*)(xp);
    float4 B1 = *(const float4*)(xp + 4);
    float4 C0 = *(const float4*)(xp + 16);
    float4 C1 = *(const float4*)(xp + 20);

    for (int l = 0; l < LL; ++l) {
        float ndel = 0.f, nuu = 0.f, nrr = 0.f;
        float4 nB0 = B0, nB1 = B1, nC0 = C0, nC1 = C1;
        if (l + 1 < LL) {
            ndel = dp[(size_t)(l + 1) * DI];
            nuu  = up[(size_t)(l + 1) * DI];
            nrr  = rp[(size_t)(l + 1) * (2 * DI)];
            const float* nx = xp + (size_t)(l + 1) * XDW;
            nB0 = *(const float4*)(nx);
            nB1 = *(const float4*)(nx + 4);
            nC0 = *(const float4*)(nx + 16);
            nC1 = *(const float4*)(nx + 20);
        }
        float Ba[8] = {B0.x, B0.y, B0.z, B0.w, B1.x, B1.y, B1.z, B1.w};
        float Ca[8] = {C0.x, C0.y, C0.z, C0.w, C1.x, C1.y, C1.z, C1.w};
        float dbu = del * uu;
        float ys = 0.f;
        if (structured) {
            float t = __expf(A0 * del);
            float p;
            if (half == 0) p = t;
            else { float t2 = t * t, t4 = t2 * t2, t8 = t4 * t4; p = t8 * t; }
            #pragma unroll
            for (int n = 0; n < 8; n++) {
                h[n] = fmaf(p, h[n], dbu * Ba[n]);
                ys = fmaf(h[n], Ca[n], ys);
                p *= t;
            }
        } else {
            #pragma unroll
            for (int n = 0; n < 8; n++) {
                float dA = __expf(A[n] * del);
                h[n] = fmaf(dA, h[n], dbu * Ba[n]);
                ys = fmaf(h[n], Ca[n], ys);
            }
        }
        ys += __shfl_xor_sync(0xffffffffu, ys, 1);
        if (half == 0) {
            float yv = fmaf(uu, Dd, ys);
            yv *= rr / (1.f + expf(-rr));           // gate
            __nv_bfloat16 hv = __float2bfloat16_rn(yv);
            yh[ybase + (size_t)l * DI] = hv;
            yl[ybase + (size_t)l * DI] = __float2bfloat16_rn(yv - __bfloat162float(hv));
        }
        del = ndel; uu = nuu; rr = nrr;
        B0 = nB0; B1 = nB1; C0 = nC0; C1 = nC1;
    }
}

// ================= host =================
static inline void launch_split(const float* src, int lda, int M, int K,
                                __nv_bfloat16* dhi, __nv_bfloat16* dlo, int Mp, int Kp) {
    int tot = Mp * (Kp / 8);
    split_kernel<<<(tot + 255) / 256, 256>>>(src, lda, M, K, dhi, dlo, Mp, Kp);
}

extern "C" void kernel_launch(void* const* d_in, const int* in_sizes, int n_in,
                              void* d_out, int out_size) {
    const int*   ids       = (const int*)  d_in[0];
    const float* emb       = (const float*)d_in[4];
    const float* norm_w    = (const float*)d_in[5];
    const float* in_proj_w = (const float*)d_in[6];
    const float* conv_w    = (const float*)d_in[7];
    const float* conv_b    = (const float*)d_in[8];
    const float* x_proj_w  = (const float*)d_in[9];
    const float* dt_proj_w = (const float*)d_in[10];
    const float* dt_proj_b = (const float*)d_in[11];
    const float* A_log     = (const float*)d_in[12];
    const float* D_param   = (const float*)d_in[13];
    const float* out_proj_w= (const float*)d_in[14];
    const float* norm_f_w  = (const float*)d_in[15];
    float* out = (float*)d_out;

    float *x, *xr, *xin, *xdbl, *delta, *xp, *op;
    cudaGetSymbolAddress((void**)&x,     g_x);
    cudaGetSymbolAddress((void**)&xr,    g_xr);
    cudaGetSymbolAddress((void**)&xin,   g_xin);
    cudaGetSymbolAddress((void**)&xdbl,  g_xdbl);
    cudaGetSymbolAddress((void**)&delta, g_delta);
    cudaGetSymbolAddress((void**)&xp,    g_xp);
    cudaGetSymbolAddress((void**)&op,    g_op);

    __nv_bfloat16 *Emb_h, *Emb_l, *Win_h, *Win_l, *Wout_h, *Wout_l;
    __nv_bfloat16 *Wx_h, *Wx_l, *Wdt_h, *Wdt_l;
    __nv_bfloat16 *Xn_h, *Xn_l, *Xin_h, *Xin_l, *Xd_h, *Xd_l, *Y_h, *Y_l;
    cudaGetSymbolAddress((void**)&Emb_h,  g_Emb_h);  cudaGetSymbolAddress((void**)&Emb_l,  g_Emb_l);
    cudaGetSymbolAddress((void**)&Win_h,  g_Win_h);  cudaGetSymbolAddress((void**)&Win_l,  g_Win_l);
    cudaGetSymbolAddress((void**)&Wout_h, g_Wout_h); cudaGetSymbolAddress((void**)&Wout_l, g_Wout_l);
    cudaGetSymbolAddress((void**)&Wx_h,   g_Wx_h);   cudaGetSymbolAddress((void**)&Wx_l,   g_Wx_l);
    cudaGetSymbolAddress((void**)&Wdt_h,  g_Wdt_h);  cudaGetSymbolAddress((void**)&Wdt_l,  g_Wdt_l);
    cudaGetSymbolAddress((void**)&Xn_h,   g_Xn_h);   cudaGetSymbolAddress((void**)&Xn_l,   g_Xn_l);
    cudaGetSymbolAddress((void**)&Xin_h,  g_Xin_h);  cudaGetSymbolAddress((void**)&Xin_l,  g_Xin_l);
    cudaGetSymbolAddress((void**)&Xd_h,   g_Xd_h);   cudaGetSymbolAddress((void**)&Xd_l,   g_Xd_l);
    cudaGetSymbolAddress((void**)&Y_h,    g_Y_h);    cudaGetSymbolAddress((void**)&Y_l,    g_Y_l);

    const int SMEM256 = 2 * STG_E * 2;        // 122880 bytes
    const int SMEM128 = 2 * 4 * MATA * 2;     // 81920 bytes
    cudaFuncSetAttribute(gemm256<0>, cudaFuncAttributeMaxDynamicSharedMemorySize, SMEM256);
    cudaFuncSetAttribute(gemm256<2>, cudaFuncAttributeMaxDynamicSharedMemorySize, SMEM256);
    cudaFuncSetAttribute(gemm128,    cudaFuncAttributeMaxDynamicSharedMemorySize, SMEM128);

    // one-time weight/emb splits
    for (int L = 0; L < NL; ++L) {
        launch_split(in_proj_w + (size_t)L * 2 * DI * DM, DM, 2 * DI, DM,
                     Win_h + (size_t)L * 2 * DI * DM, Win_l + (size_t)L * 2 * DI * DM, 2 * DI, DM);
        launch_split(out_proj_w + (size_t)L * DM * DI, DI, DM, DI,
                     Wout_h + (size_t)L * DM * DI, Wout_l + (size_t)L * DM * DI, DM, DI);
        launch_split(x_proj_w + (size_t)L * XDW * DI, DI, XDW, DI,
                     Wx_h + (size_t)L * 128 * DI, Wx_l + (size_t)L * 128 * DI, 128, DI);
        launch_split(dt_proj_w + (size_t)L * DI * DTR, DTR, DI, DTR,
                     Wdt_h + (size_t)L * DI * 64, Wdt_l + (size_t)L * DI * 64, DI, 64);
    }
    launch_split(emb, DM, VOC, DM, Emb_h, Emb_l, VOC, DM);

    embed_kernel<<<(BL * DM + 255) / 256, 256>>>(ids, emb, x);

    for (int L = 0; L < NL; ++L) {
        rmsnorm_split_kernel<<<BL, 256>>>(x, norm_w + (size_t)L * DM, Xn_h, Xn_l);

        // in_proj: (2048x768) @ (3072x768)^T -> xr
        gemm256<0><<<dim3(12, 16), 256, SMEM256>>>(
            Xn_h, Xn_l, Win_h + (size_t)L * 2 * DI * DM, Win_l + (size_t)L * 2 * DI * DM,
            xr, 2 * DI, DM, 24, 0, nullptr);

        conv_silu_split_kernel<<<(BL * DI + 255) / 256, 256>>>(
            xr, conv_w + (size_t)L * DI * 4, conv_b + (size_t)L * DI, xin, Xin_h, Xin_l);

        // x_proj split-K=8: (2048x1536) @ (80x1536)^T -> 8 partials
        gemm128<<<dim3(1, 16, 8), 256, SMEM128>>>(
            Xin_h, Xin_l, Wx_h + (size_t)L * 128 * DI, Wx_l + (size_t)L * 128 * DI,
            xp, XDW, XDW, DI, 6, (size_t)BL * XDW);
        xreduce_kernel<<<(BL * XDW + 255) / 256, 256>>>(xp, xdbl, Xd_h, Xd_l);

        // dt_proj + softplus(.. + bias): (2048x64) @ (1536x64)^T -> delta
        gemm256<2><<<dim3(6, 16), 256, SMEM256>>>(
            Xd_h, Xd_l, Wdt_h + (size_t)L * DI * 64, Wdt_l + (size_t)L * DI * 64,
            delta, DI, 64, 2, 0, dt_proj_b + (size_t)L * DI);

        scan_gate_kernel<<<(BB * DI * 2) / 128, 128>>>(
            xin, delta, xdbl, A_log + (size_t)L * DI * DS, D_param + (size_t)L * DI,
            xr, Y_h, Y_l);

        // out_proj split-K=3: (2048x1536) @ (768x1536)^T -> 3 partials; reduce-add into x
        gemm256<0><<<dim3(3, 16, 3), 256, SMEM256>>>(
            Y_h, Y_l, Wout_h + (size_t)L * DM * DI, Wout_l + (size_t)L * DM * DI,
            op, DM, DI, 16, (size_t)BL * DM, nullptr);
        oreduce_kernel<<<(BL * DM + 255) / 256, 256>>>(op, x);
    }

    rmsnorm_split_kernel<<<BL, 256>>>(x, norm_f_w, Xn_h, Xn_l);

    // lm_head: (2048x768) @ (32000x768)^T -> out
    gemm256<0><<<dim3(125, 16), 256, SMEM256>>>(
        Xn_h, Xn_l, Emb_h, Emb_l, out, VOC, DM, 24, 0, nullptr);
}

// round 15
// speedup vs baseline: 1.3892x; 1.3892x over previous
#include <cuda_runtime.h>
#include <cuda_bf16.h>
#include <math.h>
#include <stdint.h>

#define DM   768
#define DI   1536
#define DS   16
#define DTR  48
#define NL   4
#define VOC  32000
#define BB   2
#define LL   1024
#define BL   (BB*LL)      // 2048
#define XDW  (DTR + 2*DS) // 80

// ---------------- fp32 scratch ----------------
__device__ float g_x    [BL*DM];
__device__ float g_xr   [BL*2*DI];
__device__ float g_xin  [BL*DI];
__device__ float g_xdbl [BL*XDW];
__device__ float g_delta[BL*DI];
__device__ float g_xp   [8*BL*XDW];   // x_proj split-K partials
__device__ float g_op   [3*BL*DM];    // out_proj split-K partials

// ---------------- bf16 hi/lo split scratch -------------
__device__ __align__(16) __nv_bfloat16 g_Emb_h [VOC*DM];
__device__ __align__(16) __nv_bfloat16 g_Emb_l [VOC*DM];
__device__ __align__(16) __nv_bfloat16 g_Win_h [NL*2*DI*DM];
__device__ __align__(16) __nv_bfloat16 g_Win_l [NL*2*DI*DM];
__device__ __align__(16) __nv_bfloat16 g_Wout_h[NL*DM*DI];
__device__ __align__(16) __nv_bfloat16 g_Wout_l[NL*DM*DI];
__device__ __align__(16) __nv_bfloat16 g_Wx_h  [NL*128*DI];
__device__ __align__(16) __nv_bfloat16 g_Wx_l  [NL*128*DI];
__device__ __align__(16) __nv_bfloat16 g_Wdt_h [NL*DI*64];
__device__ __align__(16) __nv_bfloat16 g_Wdt_l [NL*DI*64];
__device__ __align__(16) __nv_bfloat16 g_Xn_h  [BL*DM];
__device__ __align__(16) __nv_bfloat16 g_Xn_l  [BL*DM];
__device__ __align__(16) __nv_bfloat16 g_Xin_h [BL*DI];
__device__ __align__(16) __nv_bfloat16 g_Xin_l [BL*DI];
__device__ __align__(16) __nv_bfloat16 g_Xd_h  [BL*64];
__device__ __align__(16) __nv_bfloat16 g_Xd_l  [BL*64];
__device__ __align__(16) __nv_bfloat16 g_Y_h   [BL*DI];
__device__ __align__(16) __nv_bfloat16 g_Y_l   [BL*DI];

// ================= common device helpers =================
__device__ __forceinline__ uint32_t smem_u32(const void* p) {
    uint32_t a;
    asm("{ .reg .u64 t; cvta.to.shared.u64 t, %1; cvt.u32.u64 %0, t; }" : "=r"(a) : "l"(p));
    return a;
}
__device__ __forceinline__ void mma16816(float* c, const uint32_t* a, const uint32_t* b) {
    asm volatile(
        "mma.sync.aligned.m16n8k16.row.col.f32.bf16.bf16.f32 "
        "{%0,%1,%2,%3}, {%4,%5,%6,%7}, {%8,%9}, {%0,%1,%2,%3};"
        : "+f"(c[0]), "+f"(c[1]), "+f"(c[2]), "+f"(c[3])
        : "r"(a[0]), "r"(a[1]), "r"(a[2]), "r"(a[3]), "r"(b[0]), "r"(b[1]));
}
#define CPA16(dst, src) \
    asm volatile("cp.async.cg.shared.global [%0], [%1], 16;" :: "r"(dst), "l"(src) : "memory")
#define CPA_COMMIT() asm volatile("cp.async.commit_group;" ::: "memory")
#define CPA_WAIT(n)  asm volatile("cp.async.wait_group %0;" :: "n"(n) : "memory")
#define LDSM4(r, addr) \
    asm volatile("ldmatrix.sync.aligned.m8n8.x4.shared.b16 {%0,%1,%2,%3}, [%4];" \
        : "=r"((r)[0]), "=r"((r)[1]), "=r"((r)[2]), "=r"((r)[3]) : "r"(addr))

__device__ __forceinline__ float softplusf(float v) {
    return (v > 0.f) ? v + log1pf(expf(-v)) : log1pf(expf(v));
}

// ================= split: fp32 -> bf16 hi/lo, padded row-major =============
__global__ void split_kernel(const float* __restrict__ src, int lda, int M, int K,
                             __nv_bfloat16* __restrict__ dhi,
                             __nv_bfloat16* __restrict__ dlo, int Mp, int Kp) {
    int idx = blockIdx.x * blockDim.x + threadIdx.x;
    int nkg = Kp >> 3;
    if (idx >= Mp * nkg) return;
    int r = idx / nkg;
    int k0 = (idx % nkg) << 3;
    __align__(16) __nv_bfloat16 hi[8], lo[8];
    #pragma unroll
    for (int j = 0; j < 8; j++) {
        int k = k0 + j;
        float v = (r < M && k < K) ? src[(size_t)r * lda + k] : 0.f;
        __nv_bfloat16 h = __float2bfloat16_rn(v);
        hi[j] = h;
        lo[j] = __float2bfloat16_rn(v - __bfloat162float(h));
    }
    size_t o = (size_t)r * Kp + k0;
    *(uint4*)(dhi + o) = *(const uint4*)hi;
    *(uint4*)(dlo + o) = *(const uint4*)lo;
}

// ================= gemm256: 128x256 tile, ldmatrix, cp.async 2-stage ========
// MODE: 0 = store, 2 = softplus(acc + bias[col])
#define SROW  40
#define MATA  (128*SROW)     // 5120 elems
#define MATB  (256*SROW)     // 10240 elems
#define STG_E (2*MATA + 2*MATB)   // 30720 elems per stage

template<int MODE>
__global__ __launch_bounds__(256, 1) void gemm256(const __nv_bfloat16* __restrict__ Ah_,
                                                  const __nv_bfloat16* __restrict__ Al_,
                                                  const __nv_bfloat16* __restrict__ Bh_,
                                                  const __nv_bfloat16* __restrict__ Bl_,
                                                  float* __restrict__ C, int ldc,
                                                  int Kp, int KT, size_t zstride,
                                                  const float* __restrict__ bias) {
    extern __shared__ __nv_bfloat16 sm[];
    uint32_t smb = smem_u32(sm);
    int tid = threadIdx.x;
    int m0 = blockIdx.y * 128, n0 = blockIdx.x * 256;
    int kbase = blockIdx.z * (KT * 32);
    C += (size_t)blockIdx.z * zstride;

    int lr = tid >> 2;            // 0..63
    int lk = (tid & 3) * 8;       // 0,8,16,24

    int lane = tid & 31;
    int w = tid >> 5;
    int wm = (w & 1) * 64;
    int wn = (w >> 1) * 64;
    int g = lane >> 2;
    int tig = lane & 3;

    // ldmatrix per-lane byte offsets (within a stage)
    uint32_t a_off = 2u * ((wm + (lane & 15)) * SROW + (lane >> 4) * 8);
    uint32_t b_off = 2u * ((wn + ((lane & 7) | ((lane >> 1) & 8))) * SROW
                           + ((lane >> 3) & 1) * 8);

    float acc[4][8][4];
    #pragma unroll
    for (int i = 0; i < 4; i++)
        #pragma unroll
        for (int j = 0; j < 8; j++)
            #pragma unroll
            for (int r = 0; r < 4; r++) acc[i][j][r] = 0.f;

    auto load_stage = [&](int kt, int s) {
        int k0 = kbase + kt * 32;
        uint32_t sbase = smb + 2u * (s * STG_E);
        #pragma unroll
        for (int h = 0; h < 2; h++) {
            int row = lr + 64 * h;
            size_t off = (size_t)(m0 + row) * Kp + k0 + lk;
            uint32_t d = sbase + 2u * (row * SROW + lk);
            CPA16(d,             Ah_ + off);
            CPA16(d + 2 * MATA,  Al_ + off);
        }
        #pragma unroll
        for (int h = 0; h < 4; h++) {
            int row = lr + 64 * h;
            size_t off = (size_t)(n0 + row) * Kp + k0 + lk;
            uint32_t d = sbase + 2u * (2 * MATA + row * SROW + lk);
            CPA16(d,             Bh_ + off);
            CPA16(d + 2 * MATB,  Bl_ + off);
        }
        CPA_COMMIT();
    };

    auto compute_stage = [&](int s) {
        uint32_t sbase = smb + 2u * (s * STG_E);
        #pragma unroll
        for (int ks = 0; ks < 2; ks++) {
            uint32_t abase = sbase + a_off + 2u * (ks * 16);
            uint32_t bbase = sbase + 2u * (2 * MATA) + b_off + 2u * (ks * 16);
            uint32_t fah[16], fbh[16], flo[16];
            #pragma unroll
            for (int mt = 0; mt < 4; mt++) LDSM4(&fah[mt * 4], abase + 2u * (mt * 16 * SROW));
            #pragma unroll
            for (int p = 0; p < 4; p++)  LDSM4(&fbh[p * 4], bbase + 2u * (p * 16 * SROW));
            #pragma unroll
            for (int mt = 0; mt < 4; mt++)
                #pragma unroll
                for (int nt = 0; nt < 8; nt++)
                    mma16816(acc[mt][nt], &fah[mt * 4], &fbh[(nt >> 1) * 4 + (nt & 1) * 2]);
            // A_lo pass
            #pragma unroll
            for (int mt = 0; mt < 4; mt++) LDSM4(&flo[mt * 4], abase + 2u * MATA + 2u * (mt * 16 * SROW));
            #pragma unroll
            for (int mt = 0; mt < 4; mt++)
                #pragma unroll
                for (int nt = 0; nt < 8; nt++)
                    mma16816(acc[mt][nt], &flo[mt * 4], &fbh[(nt >> 1) * 4 + (nt & 1) * 2]);
            // B_lo pass
            #pragma unroll
            for (int p = 0; p < 4; p++)  LDSM4(&flo[p * 4], bbase + 2u * MATB + 2u * (p * 16 * SROW));
            #pragma unroll
            for (int mt = 0; mt < 4; mt++)
                #pragma unroll
                for (int nt = 0; nt < 8; nt++)
                    mma16816(acc[mt][nt], &fah[mt * 4], &flo[(nt >> 1) * 4 + (nt & 1) * 2]);
        }
    };

    load_stage(0, 0);
    for (int kt = 0; kt < KT; kt++) {
        int s = kt & 1;
        if (kt + 1 < KT) { load_stage(kt + 1, s ^ 1); CPA_WAIT(1); }
        else             { CPA_WAIT(0); }
        __syncthreads();
        compute_stage(s);
        __syncthreads();
    }

    // epilogue (all N multiples of 256 -> no guards)
    #pragma unroll
    for (int mt = 0; mt < 4; mt++) {
        #pragma unroll
        for (int nt = 0; nt < 8; nt++) {
            int r = m0 + wm + mt * 16 + g;
            int c = n0 + wn + nt * 8 + 2 * tig;
            float* p0 = C + (size_t)r * ldc + c;
            float* p1 = C + (size_t)(r + 8) * ldc + c;
            float v0 = acc[mt][nt][0], v1 = acc[mt][nt][1];
            float v2 = acc[mt][nt][2], v3 = acc[mt][nt][3];
            if (MODE == 2) {
                float b0 = bias[c], b1 = bias[c + 1];
                v0 = softplusf(v0 + b0); v1 = softplusf(v1 + b1);
                v2 = softplusf(v2 + b0); v3 = softplusf(v3 + b1);
            }
            p0[0] = v0; p0[1] = v1;
            p1[0] = v2; p1[1] = v3;
        }
    }
}

// ================= gemm128: 128x128 tile (x_proj, split-K) =================
__global__ __launch_bounds__(256) void gemm128(const __nv_bfloat16* __restrict__ Ah_,
                                               const __nv_bfloat16* __restrict__ Al_,
                                               const __nv_bfloat16* __restrict__ Bh_,
                                               const __nv_bfloat16* __restrict__ Bl_,
                                               float* __restrict__ C, int ldc,
                                               int N, int Kp, int KT, size_t zstride) {
    extern __shared__ __nv_bfloat16 sm[];
    uint32_t smb = smem_u32(sm);
    int tid = threadIdx.x;
    int m0 = blockIdx.y * 128, n0 = blockIdx.x * 128;
    int kbase = blockIdx.z * (KT * 32);
    C += (size_t)blockIdx.z * zstride;

    int lrow = tid >> 2;
    int lkc = (tid & 3) * 8;
    int lane = tid & 31;
    int w = tid >> 5;
    int wm = (w & 1) * 64;
    int wn = (w >> 1) * 32;
    int g = lane >> 2;
    int tig = lane & 3;

    uint32_t a_off = 2u * ((wm + (lane & 15)) * SROW + (lane >> 4) * 8);
    uint32_t b_off = 2u * ((wn + ((lane & 7) | ((lane >> 1) & 8))) * SROW
                           + ((lane >> 3) & 1) * 8);

    float acc[4][4][4];
    #pragma unroll
    for (int i = 0; i < 4; i++)
        #pragma unroll
        for (int j = 0; j < 4; j++)
            #pragma unroll
            for (int r = 0; r < 4; r++) acc[i][j][r] = 0.f;

    auto load_stage = [&](int kt, int s) {
        int k0 = kbase + kt * 32;
        #pragma unroll
        for (int h = 0; h < 2; h++) {
            int row = lrow + 64 * h;
            size_t aoff = (size_t)(m0 + row) * Kp + k0 + lkc;
            size_t boff = (size_t)(n0 + row) * Kp + k0 + lkc;
            uint32_t sb = smb + (uint32_t)((s * 4 * MATA + row * SROW + lkc) * 2);
            CPA16(sb,                Ah_ + aoff);
            CPA16(sb + MATA * 2,     Al_ + aoff);
            CPA16(sb + 2 * MATA * 2, Bh_ + boff);
            CPA16(sb + 3 * MATA * 2, Bl_ + boff);
        }
        CPA_COMMIT();
    };

    auto compute_stage = [&](int s) {
        uint32_t sbase = smb + 2u * (s * 4 * MATA);
        #pragma unroll
        for (int ks = 0; ks < 2; ks++) {
            uint32_t abase = sbase + a_off + 2u * (ks * 16);
            uint32_t bbase = sbase + 2u * (2 * MATA) + b_off + 2u * (ks * 16);
            uint32_t fah[16], fbh[8], flo[16];
            #pragma unroll
            for (int mt = 0; mt < 4; mt++) LDSM4(&fah[mt * 4], abase + 2u * (mt * 16 * SROW));
            #pragma unroll
            for (int p = 0; p < 2; p++)  LDSM4(&fbh[p * 4], bbase + 2u * (p * 16 * SROW));
            #pragma unroll
            for (int mt = 0; mt < 4; mt++)
                #pragma unroll
                for (int nt = 0; nt < 4; nt++)
                    mma16816(acc[mt][nt], &fah[mt * 4], &fbh[(nt >> 1) * 4 + (nt & 1) * 2]);
            #pragma unroll
            for (int mt = 0; mt < 4; mt++) LDSM4(&flo[mt * 4], abase + 2u * MATA + 2u * (mt * 16 * SROW));
            #pragma unroll
            for (int mt = 0; mt < 4; mt++)
                #pragma unroll
                for (int nt = 0; nt < 4; nt++)
                    mma16816(acc[mt][nt], &flo[mt * 4], &fbh[(nt >> 1) * 4 + (nt & 1) * 2]);
            #pragma unroll
            for (int p = 0; p < 2; p++)  LDSM4(&flo[p * 4], bbase + 2u * MATA + 2u * (p * 16 * SROW));
            #pragma unroll
            for (int mt = 0; mt < 4; mt++)
                #pragma unroll
                for (int nt = 0; nt < 4; nt++)
                    mma16816(acc[mt][nt], &fah[mt * 4], &flo[(nt >> 1) * 4 + (nt & 1) * 2]);
        }
    };

    load_stage(0, 0);
    for (int kt = 0; kt < KT; kt++) {
        int s = kt & 1;
        if (kt + 1 < KT) { load_stage(kt + 1, s ^ 1); CPA_WAIT(1); }
        else             { CPA_WAIT(0); }
        __syncthreads();
        compute_stage(s);
        __syncthreads();
    }

    #pragma unroll
    for (int mt = 0; mt < 4; mt++) {
        #pragma unroll
        for (int nt = 0; nt < 4; nt++) {
            int r = m0 + wm + mt * 16 + g;
            int c = n0 + wn + nt * 8 + 2 * tig;
            if (c < N) {
                float* p0 = C + (size_t)r * ldc + c;
                float* p1 = C + (size_t)(r + 8) * ldc + c;
                p0[0] = acc[mt][nt][0]; p1[0] = acc[mt][nt][2];
                if (c + 1 < N) { p0[1] = acc[mt][nt][1]; p1[1] = acc[mt][nt][3]; }
            }
        }
    }
}

// ================= reduces =================
__global__ void xreduce_kernel(const float* __restrict__ xp, float* __restrict__ xdbl,
                               __nv_bfloat16* __restrict__ xdh, __nv_bfloat16* __restrict__ xdl) {
    int i = blockIdx.x * blockDim.x + threadIdx.x;
    if (i >= BL * XDW) return;
    float s = 0.f;
    #pragma unroll
    for (int z = 0; z < 8; z++) s += xp[(size_t)z * BL * XDW + i];
    xdbl[i] = s;
    int c = i % XDW, r = i / XDW;
    if (c < 64) {
        __nv_bfloat16 h = __float2bfloat16_rn(s);
        xdh[(size_t)r * 64 + c] = h;
        xdl[(size_t)r * 64 + c] = __float2bfloat16_rn(s - __bfloat162float(h));
    }
}
__global__ void oreduce_kernel(const float* __restrict__ p, float* __restrict__ x) {
    int i = blockIdx.x * blockDim.x + threadIdx.x;
    if (i >= BL * DM) return;
    x[i] += p[i] + p[(size_t)BL * DM + i] + p[(size_t)2 * BL * DM + i];
}

// ================= elementwise =================
__global__ void embed_kernel(const int* __restrict__ ids, const float* __restrict__ emb,
                             float* __restrict__ x) {
    int i = blockIdx.x * blockDim.x + threadIdx.x;
    if (i >= BL * DM) return;
    int r = i / DM, c = i % DM;
    x[i] = emb[(size_t)ids[r] * DM + c];
}

__global__ __launch_bounds__(256) void rmsnorm_split_kernel(const float* __restrict__ x,
                                                            const float* __restrict__ w,
                                                            __nv_bfloat16* __restrict__ oh,
                                                            __nv_bfloat16* __restrict__ ol) {
    int row = blockIdx.x;
    const float* xrow = x + (size_t)row * DM;
    float s = 0.f;
    for (int c = threadIdx.x; c < DM; c += 256) { float v = xrow[c]; s = fmaf(v, v, s); }
    #pragma unroll
    for (int off = 16; off; off >>= 1) s += __shfl_xor_sync(0xffffffffu, s, off);
    __shared__ float red[8];
    if ((threadIdx.x & 31) == 0) red[threadIdx.x >> 5] = s;
    __syncthreads();
    float tot = red[0] + red[1] + red[2] + red[3] + red[4] + red[5] + red[6] + red[7];
    float sc = rsqrtf(tot * (1.0f / DM) + 1e-5f);
    for (int c = threadIdx.x; c < DM; c += 256) {
        float v = xrow[c] * sc * w[c];
        __nv_bfloat16 h = __float2bfloat16_rn(v);
        oh[(size_t)row * DM + c] = h;
        ol[(size_t)row * DM + c] = __float2bfloat16_rn(v - __bfloat162float(h));
    }
}

__global__ void conv_silu_split_kernel(const float* __restrict__ xr, const float* __restrict__ cw,
                                       const float* __restrict__ cb, float* __restrict__ xin,
                                       __nv_bfloat16* __restrict__ xih, __nv_bfloat16* __restrict__ xil) {
    int i = blockIdx.x * blockDim.x + threadIdx.x;
    if (i >= BL * DI) return;
    int d = i % DI;
    int bl = i / DI;
    int l = bl % LL;
    float w0 = cw[d * 4], w1 = cw[d * 4 + 1], w2 = cw[d * 4 + 2], w3 = cw[d * 4 + 3];
    const float* base = xr + (size_t)bl * (2 * DI) + d;
    float acc = cb[d];
    if (l >= 3) acc = fmaf(w0, base[-3 * (2 * DI)], acc);
    if (l >= 2) acc = fmaf(w1, base[-2 * (2 * DI)], acc);
    if (l >= 1) acc = fmaf(w2, base[-1 * (2 * DI)], acc);
    acc = fmaf(w3, base[0], acc);
    float v = acc / (1.f + expf(-acc));
    xin[i] = v;
    __nv_bfloat16 h = __float2bfloat16_rn(v);
    xih[i] = h;
    xil[i] = __float2bfloat16_rn(v - __bfloat162float(h));
}

// ---------------- selective scan + fused gate + bf16 split ----------------
__global__ __launch_bounds__(128) void scan_gate_kernel(const float* __restrict__ u,
                                                        const float* __restrict__ delta,
                                                        const float* __restrict__ xdbl,
                                                        const float* __restrict__ A_log,
                                                        const float* __restrict__ Dp,
                                                        const float* __restrict__ xr,
                                                        __nv_bfloat16* __restrict__ yh,
                                                        __nv_bfloat16* __restrict__ yl) {
    int tid = blockIdx.x * blockDim.x + threadIdx.x;
    if (tid >= BB * DI * 2) return;
    int half = tid & 1;
    int pair = tid >> 1;
    int d = pair % DI;
    int b = pair / DI;

    float A[8];
    float A0 = -expf(A_log[d * DS]);
    bool structured = true;
    #pragma unroll
    for (int n = 0; n < 8; n++) {
        int ng = half * 8 + n;
        A[n] = -expf(A_log[d * DS + ng]);
        float e = (float)(ng + 1) * A0;
        if (fabsf(A[n] - e) > 1e-3f * fabsf(e)) structured = false;
    }
    float Dd = Dp[d];
    float h[8];
    #pragma unroll
    for (int n = 0; n < 8; n++) h[n] = 0.f;

    const float* up = u + (size_t)b * LL * DI + d;
    const float* dp = delta + (size_t)b * LL * DI + d;
    const float* xp = xdbl + (size_t)b * LL * XDW + DTR + half * 8;
    const float* rp = xr + (size_t)b * LL * (2 * DI) + DI + d;
    size_t ybase = (size_t)b * LL * DI + d;

    float del = dp[0], uu = up[0], rr = rp[0];
    float4 B0 = *(const float4*)(xp);
    float4 B1 = *(const float4*)(xp + 4);
    float4 C0 = *(const float4*)(xp + 16);
    float4 C1 = *(const float4*)(xp + 20);

    for (int l = 0; l < LL; ++l) {
        float ndel = 0.f, nuu = 0.f, nrr = 0.f;
        float4 nB0 = B0, nB1 = B1, nC0 = C0, nC1 = C1;
        if (l + 1 < LL) {
            ndel = dp[(size_t)(l + 1) * DI];
            nuu  = up[(size_t)(l + 1) * DI];
            nrr  = rp[(size_t)(l + 1) * (2 * DI)];
            const float* nx = xp + (size_t)(l + 1) * XDW;
            nB0 = *(const float4*)(nx);
            nB1 = *(const float4*)(nx + 4);
            nC0 = *(const float4*)(nx + 16);
            nC1 = *(const float4*)(nx + 20);
        }
        float Ba[8] = {B0.x, B0.y, B0.z, B0.w, B1.x, B1.y, B1.z, B1.w};
        float Ca[8] = {C0.x, C0.y, C0.z, C0.w, C1.x, C1.y, C1.z, C1.w};
        float dbu = del * uu;
        float ys = 0.f;
        if (structured) {
            float t = __expf(A0 * del);
            float p;
            if (half == 0) p = t;
            else { float t2 = t * t, t4 = t2 * t2, t8 = t4 * t4; p = t8 * t; }
            #pragma unroll
            for (int n = 0; n < 8; n++) {
                h[n] = fmaf(p, h[n], dbu * Ba[n]);
                ys = fmaf(h[n], Ca[n], ys);
                p *= t;
            }
        } else {
            #pragma unroll
            for (int n = 0; n < 8; n++) {
                float dA = __expf(A[n] * del);
                h[n] = fmaf(dA, h[n], dbu * Ba[n]);
                ys = fmaf(h[n], Ca[n], ys);
            }
        }
        ys += __shfl_xor_sync(0xffffffffu, ys, 1);
        if (half == 0) {
            float yv = fmaf(uu, Dd, ys);
            yv *= rr / (1.f + expf(-rr));           // gate
            __nv_bfloat16 hv = __float2bfloat16_rn(yv);
            yh[ybase + (size_t)l * DI] = hv;
            yl[ybase + (size_t)l * DI] = __float2bfloat16_rn(yv - __bfloat162float(hv));
        }
        del = ndel; uu = nuu; rr = nrr;
        B0 = nB0; B1 = nB1; C0 = nC0; C1 = nC1;
    }
}

// ================= host =================
static inline void launch_split(const float* src, int lda, int M, int K,
                                __nv_bfloat16* dhi, __nv_bfloat16* dlo, int Mp, int Kp) {
    int tot = Mp * (Kp / 8);
    split_kernel<<<(tot + 255) / 256, 256>>>(src, lda, M, K, dhi, dlo, Mp, Kp);
}

extern "C" void kernel_launch(void* const* d_in, const int* in_sizes, int n_in,
                              void* d_out, int out_size) {
    const int*   ids       = (const int*)  d_in[0];
    const float* emb       = (const float*)d_in[4];
    const float* norm_w    = (const float*)d_in[5];
    const float* in_proj_w = (const float*)d_in[6];
    const float* conv_w    = (const float*)d_in[7];
    const float* conv_b    = (const float*)d_in[8];
    const float* x_proj_w  = (const float*)d_in[9];
    const float* dt_proj_w = (const float*)d_in[10];
    const float* dt_proj_b = (const float*)d_in[11];
    const float* A_log     = (const float*)d_in[12];
    const float* D_param   = (const float*)d_in[13];
    const float* out_proj_w= (const float*)d_in[14];
    const float* norm_f_w  = (const float*)d_in[15];
    float* out = (float*)d_out;

    float *x, *xr, *xin, *xdbl, *delta, *xp, *op;
    cudaGetSymbolAddress((void**)&x,     g_x);
    cudaGetSymbolAddress((void**)&xr,    g_xr);
    cudaGetSymbolAddress((void**)&xin,   g_xin);
    cudaGetSymbolAddress((void**)&xdbl,  g_xdbl);
    cudaGetSymbolAddress((void**)&delta, g_delta);
    cudaGetSymbolAddress((void**)&xp,    g_xp);
    cudaGetSymbolAddress((void**)&op,    g_op);

    __nv_bfloat16 *Emb_h, *Emb_l, *Win_h, *Win_l, *Wout_h, *Wout_l;
    __nv_bfloat16 *Wx_h, *Wx_l, *Wdt_h, *Wdt_l;
    __nv_bfloat16 *Xn_h, *Xn_l, *Xin_h, *Xin_l, *Xd_h, *Xd_l, *Y_h, *Y_l;
    cudaGetSymbolAddress((void**)&Emb_h,  g_Emb_h);  cudaGetSymbolAddress((void**)&Emb_l,  g_Emb_l);
    cudaGetSymbolAddress((void**)&Win_h,  g_Win_h);  cudaGetSymbolAddress((void**)&Win_l,  g_Win_l);
    cudaGetSymbolAddress((void**)&Wout_h, g_Wout_h); cudaGetSymbolAddress((void**)&Wout_l, g_Wout_l);
    cudaGetSymbolAddress((void**)&Wx_h,   g_Wx_h);   cudaGetSymbolAddress((void**)&Wx_l,   g_Wx_l);
    cudaGetSymbolAddress((void**)&Wdt_h,  g_Wdt_h);  cudaGetSymbolAddress((void**)&Wdt_l,  g_Wdt_l);
    cudaGetSymbolAddress((void**)&Xn_h,   g_Xn_h);   cudaGetSymbolAddress((void**)&Xn_l,   g_Xn_l);
    cudaGetSymbolAddress((void**)&Xin_h,  g_Xin_h);  cudaGetSymbolAddress((void**)&Xin_l,  g_Xin_l);
    cudaGetSymbolAddress((void**)&Xd_h,   g_Xd_h);   cudaGetSymbolAddress((void**)&Xd_l,   g_Xd_l);
    cudaGetSymbolAddress((void**)&Y_h,    g_Y_h);    cudaGetSymbolAddress((void**)&Y_l,    g_Y_l);

    const int SMEM256 = 2 * STG_E * 2;        // 122880 bytes
    const int SMEM128 = 2 * 4 * MATA * 2;     // 81920 bytes
    cudaFuncSetAttribute(gemm256<0>, cudaFuncAttributeMaxDynamicSharedMemorySize, SMEM256);
    cudaFuncSetAttribute(gemm256<2>, cudaFuncAttributeMaxDynamicSharedMemorySize, SMEM256);
    cudaFuncSetAttribute(gemm128,    cudaFuncAttributeMaxDynamicSharedMemorySize, SMEM128);

    // one-time weight/emb splits
    for (int L = 0; L < NL; ++L) {
        launch_split(in_proj_w + (size_t)L * 2 * DI * DM, DM, 2 * DI, DM,
                     Win_h + (size_t)L * 2 * DI * DM, Win_l + (size_t)L * 2 * DI * DM, 2 * DI, DM);
        launch_split(out_proj_w + (size_t)L * DM * DI, DI, DM, DI,
                     Wout_h + (size_t)L * DM * DI, Wout_l + (size_t)L * DM * DI, DM, DI);
        launch_split(x_proj_w + (size_t)L * XDW * DI, DI, XDW, DI,
                     Wx_h + (size_t)L * 128 * DI, Wx_l + (size_t)L * 128 * DI, 128, DI);
        launch_split(dt_proj_w + (size_t)L * DI * DTR, DTR, DI, DTR,
                     Wdt_h + (size_t)L * DI * 64, Wdt_l + (size_t)L * DI * 64, DI, 64);
    }
    launch_split(emb, DM, VOC, DM, Emb_h, Emb_l, VOC, DM);

    embed_kernel<<<(BL * DM + 255) / 256, 256>>>(ids, emb, x);

    for (int L = 0; L < NL; ++L) {
        rmsnorm_split_kernel<<<BL, 256>>>(x, norm_w + (size_t)L * DM, Xn_h, Xn_l);

        // in_proj: (2048x768) @ (3072x768)^T -> xr
        gemm256<0><<<dim3(12, 16), 256, SMEM256>>>(
            Xn_h, Xn_l, Win_h + (size_t)L * 2 * DI * DM, Win_l + (size_t)L * 2 * DI * DM,
            xr, 2 * DI, DM, 24, 0, nullptr);

        conv_silu_split_kernel<<<(BL * DI + 255) / 256, 256>>>(
            xr, conv_w + (size_t)L * DI * 4, conv_b + (size_t)L * DI, xin, Xin_h, Xin_l);

        // x_proj split-K=8: (2048x1536) @ (80x1536)^T -> 8 partials
        gemm128<<<dim3(1, 16, 8), 256, SMEM128>>>(
            Xin_h, Xin_l, Wx_h + (size_t)L * 128 * DI, Wx_l + (size_t)L * 128 * DI,
            xp, XDW, XDW, DI, 6, (size_t)BL * XDW);
        xreduce_kernel<<<(BL * XDW + 255) / 256, 256>>>(xp, xdbl, Xd_h, Xd_l);

        // dt_proj + softplus(.. + bias): (2048x64) @ (1536x64)^T -> delta
        gemm256<2><<<dim3(6, 16), 256, SMEM256>>>(
            Xd_h, Xd_l, Wdt_h + (size_t)L * DI * 64, Wdt_l + (size_t)L * DI * 64,
            delta, DI, 64, 2, 0, dt_proj_b + (size_t)L * DI);

        scan_gate_kernel<<<(BB * DI * 2) / 128, 128>>>(
            xin, delta, xdbl, A_log + (size_t)L * DI * DS, D_param + (size_t)L * DI,
            xr, Y_h, Y_l);

        // out_proj split-K=3: (2048x1536) @ (768x1536)^T -> 3 partials; reduce-add into x
        gemm256<0><<<dim3(3, 16, 3), 256, SMEM256>>>(
            Y_h, Y_l, Wout_h + (size_t)L * DM * DI, Wout_l + (size_t)L * DM * DI,
            op, DM, DI, 16, (size_t)BL * DM, nullptr);
        oreduce_kernel<<<(BL * DM + 255) / 256, 256>>>(op, x);
    }

    rmsnorm_split_kernel<<<BL, 256>>>(x, norm_f_w, Xn_h, Xn_l);

    // lm_head: (2048x768) @ (32000x768)^T -> out
    gemm256<0><<<dim3(125, 16), 256, SMEM256>>>(
        Xn_h, Xn_l, Emb_h, Emb_l, out, VOC, DM, 24, 0, nullptr);
}

// round 16
// speedup vs baseline: 1.4197x; 1.0220x over previous
#include <cuda_runtime.h>
#include <cuda_bf16.h>
#include <math.h>
#include <stdint.h>

#define DM   768
#define DI   1536
#define DS   16
#define DTR  48
#define NL   4
#define VOC  32000
#define BB   2
#define LL   1024
#define BL   (BB*LL)      // 2048
#define XDW  (DTR + 2*DS) // 80

// ---------------- fp32 scratch ----------------
__device__ float g_x    [BL*DM];
__device__ float g_xr   [BL*2*DI];
__device__ float g_xin  [BL*DI];
__device__ float g_xdbl [BL*XDW];
__device__ float g_delta[BL*DI];
__device__ float g_xp   [8*BL*XDW];   // x_proj split-K partials
__device__ float g_op   [3*BL*DM];    // out_proj split-K partials

// ---------------- bf16 hi/lo split scratch -------------
__device__ __align__(16) __nv_bfloat16 g_Emb_h [VOC*DM];
__device__ __align__(16) __nv_bfloat16 g_Emb_l [VOC*DM];
__device__ __align__(16) __nv_bfloat16 g_Win_h [NL*2*DI*DM];
__device__ __align__(16) __nv_bfloat16 g_Win_l [NL*2*DI*DM];
__device__ __align__(16) __nv_bfloat16 g_Wout_h[NL*DM*DI];
__device__ __align__(16) __nv_bfloat16 g_Wout_l[NL*DM*DI];
__device__ __align__(16) __nv_bfloat16 g_Wx_h  [NL*128*DI];
__device__ __align__(16) __nv_bfloat16 g_Wx_l  [NL*128*DI];
__device__ __align__(16) __nv_bfloat16 g_Wdt_h [NL*DI*64];
__device__ __align__(16) __nv_bfloat16 g_Wdt_l [NL*DI*64];
__device__ __align__(16) __nv_bfloat16 g_Xn_h  [BL*DM];
__device__ __align__(16) __nv_bfloat16 g_Xn_l  [BL*DM];
__device__ __align__(16) __nv_bfloat16 g_Xin_h [BL*DI];
__device__ __align__(16) __nv_bfloat16 g_Xin_l [BL*DI];
__device__ __align__(16) __nv_bfloat16 g_Xd_h  [BL*64];
__device__ __align__(16) __nv_bfloat16 g_Xd_l  [BL*64];
__device__ __align__(16) __nv_bfloat16 g_Y_h   [BL*DI];
__device__ __align__(16) __nv_bfloat16 g_Y_l   [BL*DI];

// ================= common device helpers =================
__device__ __forceinline__ uint32_t smem_u32(const void* p) {
    uint32_t a;
    asm("{ .reg .u64 t; cvta.to.shared.u64 t, %1; cvt.u32.u64 %0, t; }" : "=r"(a) : "l"(p));
    return a;
}
__device__ __forceinline__ void mma16816(float* c, const uint32_t* a, const uint32_t* b) {
    asm volatile(
        "mma.sync.aligned.m16n8k16.row.col.f32.bf16.bf16.f32 "
        "{%0,%1,%2,%3}, {%4,%5,%6,%7}, {%8,%9}, {%0,%1,%2,%3};"
        : "+f"(c[0]), "+f"(c[1]), "+f"(c[2]), "+f"(c[3])
        : "r"(a[0]), "r"(a[1]), "r"(a[2]), "r"(a[3]), "r"(b[0]), "r"(b[1]));
}
#define CPA16(dst, src) \
    asm volatile("cp.async.cg.shared.global [%0], [%1], 16;" :: "r"(dst), "l"(src) : "memory")
#define CPA_COMMIT() asm volatile("cp.async.commit_group;" ::: "memory")
#define CPA_WAIT(n)  asm volatile("cp.async.wait_group %0;" :: "n"(n) : "memory")
#define LDSM4(r, addr) \
    asm volatile("ldmatrix.sync.aligned.m8n8.x4.shared.b16 {%0,%1,%2,%3}, [%4];" \
        : "=r"((r)[0]), "=r"((r)[1]), "=r"((r)[2]), "=r"((r)[3]) : "r"(addr))

__device__ __forceinline__ float softplusf(float v) {
    return (v > 0.f) ? v + log1pf(expf(-v)) : log1pf(expf(v));
}

// ================= split: fp32 -> bf16 hi/lo, padded row-major =============
__global__ void split_kernel(const float* __restrict__ src, int lda, int M, int K,
                             __nv_bfloat16* __restrict__ dhi,
                             __nv_bfloat16* __restrict__ dlo, int Mp, int Kp) {
    int idx = blockIdx.x * blockDim.x + threadIdx.x;
    int nkg = Kp >> 3;
    if (idx >= Mp * nkg) return;
    int r = idx / nkg;
    int k0 = (idx % nkg) << 3;
    __align__(16) __nv_bfloat16 hi[8], lo[8];
    #pragma unroll
    for (int j = 0; j < 8; j++) {
        int k = k0 + j;
        float v = (r < M && k < K) ? src[(size_t)r * lda + k] : 0.f;
        __nv_bfloat16 h = __float2bfloat16_rn(v);
        hi[j] = h;
        lo[j] = __float2bfloat16_rn(v - __bfloat162float(h));
    }
    size_t o = (size_t)r * Kp + k0;
    *(uint4*)(dhi + o) = *(const uint4*)hi;
    *(uint4*)(dlo + o) = *(const uint4*)lo;
}

// ================= gemm256: 128x256 tile, ldmatrix, cp.async 2-stage ========
// MODE: 0 = store, 2 = softplus(acc + bias[col])
#define SROW  40
#define MATA  (128*SROW)     // 5120 elems
#define MATB  (256*SROW)     // 10240 elems
#define STG_E (2*MATA + 2*MATB)   // 30720 elems per stage

template<int MODE>
__global__ __launch_bounds__(256, 1) void gemm256(const __nv_bfloat16* __restrict__ Ah_,
                                                  const __nv_bfloat16* __restrict__ Al_,
                                                  const __nv_bfloat16* __restrict__ Bh_,
                                                  const __nv_bfloat16* __restrict__ Bl_,
                                                  float* __restrict__ C, int ldc,
                                                  int Kp, int KT, size_t zstride,
                                                  const float* __restrict__ bias) {
    extern __shared__ __nv_bfloat16 sm[];
    uint32_t smb = smem_u32(sm);
    int tid = threadIdx.x;
    int m0 = blockIdx.y * 128, n0 = blockIdx.x * 256;
    int kbase = blockIdx.z * (KT * 32);
    C += (size_t)blockIdx.z * zstride;

    int lr = tid >> 2;            // 0..63
    int lk = (tid & 3) * 8;       // 0,8,16,24

    int lane = tid & 31;
    int w = tid >> 5;
    int wm = (w & 1) * 64;
    int wn = (w >> 1) * 64;
    int g = lane >> 2;
    int tig = lane & 3;

    // ldmatrix per-lane byte offsets (within a stage)
    uint32_t a_off = 2u * ((wm + (lane & 15)) * SROW + (lane >> 4) * 8);
    uint32_t b_off = 2u * ((wn + ((lane & 7) | ((lane >> 1) & 8))) * SROW
                           + ((lane >> 3) & 1) * 8);

    float acc[4][8][4];
    #pragma unroll
    for (int i = 0; i < 4; i++)
        #pragma unroll
        for (int j = 0; j < 8; j++)
            #pragma unroll
            for (int r = 0; r < 4; r++) acc[i][j][r] = 0.f;

    auto load_stage = [&](int kt, int s) {
        int k0 = kbase + kt * 32;
        uint32_t sbase = smb + 2u * (s * STG_E);
        #pragma unroll
        for (int h = 0; h < 2; h++) {
            int row = lr + 64 * h;
            size_t off = (size_t)(m0 + row) * Kp + k0 + lk;
            uint32_t d = sbase + 2u * (row * SROW + lk);
            CPA16(d,             Ah_ + off);
            CPA16(d + 2 * MATA,  Al_ + off);
        }
        #pragma unroll
        for (int h = 0; h < 4; h++) {
            int row = lr + 64 * h;
            size_t off = (size_t)(n0 + row) * Kp + k0 + lk;
            uint32_t d = sbase + 2u * (2 * MATA + row * SROW + lk);
            CPA16(d,             Bh_ + off);
            CPA16(d + 2 * MATB,  Bl_ + off);
        }
        CPA_COMMIT();
    };

    auto compute_stage = [&](int s) {
        uint32_t sbase = smb + 2u * (s * STG_E);
        #pragma unroll
        for (int ks = 0; ks < 2; ks++) {
            uint32_t abase = sbase + a_off + 2u * (ks * 16);
            uint32_t bbase = sbase + 2u * (2 * MATA) + b_off + 2u * (ks * 16);
            uint32_t fah[16], fbh[16], flo[16];
            #pragma unroll
            for (int mt = 0; mt < 4; mt++) LDSM4(&fah[mt * 4], abase + 2u * (mt * 16 * SROW));
            #pragma unroll
            for (int p = 0; p < 4; p++)  LDSM4(&fbh[p * 4], bbase + 2u * (p * 16 * SROW));
            #pragma unroll
            for (int mt = 0; mt < 4; mt++)
                #pragma unroll
                for (int nt = 0; nt < 8; nt++)
                    mma16816(acc[mt][nt], &fah[mt * 4], &fbh[(nt >> 1) * 4 + (nt & 1) * 2]);
            // A_lo pass
            #pragma unroll
            for (int mt = 0; mt < 4; mt++) LDSM4(&flo[mt * 4], abase + 2u * MATA + 2u * (mt * 16 * SROW));
            #pragma unroll
            for (int mt = 0; mt < 4; mt++)
                #pragma unroll
                for (int nt = 0; nt < 8; nt++)
                    mma16816(acc[mt][nt], &flo[mt * 4], &fbh[(nt >> 1) * 4 + (nt & 1) * 2]);
            // B_lo pass
            #pragma unroll
            for (int p = 0; p < 4; p++)  LDSM4(&flo[p * 4], bbase + 2u * MATB + 2u * (p * 16 * SROW));
            #pragma unroll
            for (int mt = 0; mt < 4; mt++)
                #pragma unroll
                for (int nt = 0; nt < 8; nt++)
                    mma16816(acc[mt][nt], &fah[mt * 4], &flo[(nt >> 1) * 4 + (nt & 1) * 2]);
        }
    };

    load_stage(0, 0);
    for (int kt = 0; kt < KT; kt++) {
        int s = kt & 1;
        if (kt + 1 < KT) { load_stage(kt + 1, s ^ 1); CPA_WAIT(1); }
        else             { CPA_WAIT(0); }
        __syncthreads();
        compute_stage(s);
        __syncthreads();
    }

    // epilogue (all N multiples of 256 -> no guards)
    #pragma unroll
    for (int mt = 0; mt < 4; mt++) {
        #pragma unroll
        for (int nt = 0; nt < 8; nt++) {
            int r = m0 + wm + mt * 16 + g;
            int c = n0 + wn + nt * 8 + 2 * tig;
            float* p0 = C + (size_t)r * ldc + c;
            float* p1 = C + (size_t)(r + 8) * ldc + c;
            float v0 = acc[mt][nt][0], v1 = acc[mt][nt][1];
            float v2 = acc[mt][nt][2], v3 = acc[mt][nt][3];
            if (MODE == 2) {
                float b0 = bias[c], b1 = bias[c + 1];
                v0 = softplusf(v0 + b0); v1 = softplusf(v1 + b1);
                v2 = softplusf(v2 + b0); v3 = softplusf(v3 + b1);
            }
            p0[0] = v0; p0[1] = v1;
            p1[0] = v2; p1[1] = v3;
        }
    }
}

// ================= gemm128: 128x128 tile (x_proj, split-K) =================
__global__ __launch_bounds__(256) void gemm128(const __nv_bfloat16* __restrict__ Ah_,
                                               const __nv_bfloat16* __restrict__ Al_,
                                               const __nv_bfloat16* __restrict__ Bh_,
                                               const __nv_bfloat16* __restrict__ Bl_,
                                               float* __restrict__ C, int ldc,
                                               int N, int Kp, int KT, size_t zstride) {
    extern __shared__ __nv_bfloat16 sm[];
    uint32_t smb = smem_u32(sm);
    int tid = threadIdx.x;
    int m0 = blockIdx.y * 128, n0 = blockIdx.x * 128;
    int kbase = blockIdx.z * (KT * 32);
    C += (size_t)blockIdx.z * zstride;

    int lrow = tid >> 2;
    int lkc = (tid & 3) * 8;
    int lane = tid & 31;
    int w = tid >> 5;
    int wm = (w & 1) * 64;
    int wn = (w >> 1) * 32;
    int g = lane >> 2;
    int tig = lane & 3;

    uint32_t a_off = 2u * ((wm + (lane & 15)) * SROW + (lane >> 4) * 8);
    uint32_t b_off = 2u * ((wn + ((lane & 7) | ((lane >> 1) & 8))) * SROW
                           + ((lane >> 3) & 1) * 8);

    float acc[4][4][4];
    #pragma unroll
    for (int i = 0; i < 4; i++)
        #pragma unroll
        for (int j = 0; j < 4; j++)
            #pragma unroll
            for (int r = 0; r < 4; r++) acc[i][j][r] = 0.f;

    auto load_stage = [&](int kt, int s) {
        int k0 = kbase + kt * 32;
        #pragma unroll
        for (int h = 0; h < 2; h++) {
            int row = lrow + 64 * h;
            size_t aoff = (size_t)(m0 + row) * Kp + k0 + lkc;
            size_t boff = (size_t)(n0 + row) * Kp + k0 + lkc;
            uint32_t sb = smb + (uint32_t)((s * 4 * MATA + row * SROW + lkc) * 2);
            CPA16(sb,                Ah_ + aoff);
            CPA16(sb + MATA * 2,     Al_ + aoff);
            CPA16(sb + 2 * MATA * 2, Bh_ + boff);
            CPA16(sb + 3 * MATA * 2, Bl_ + boff);
        }
        CPA_COMMIT();
    };

    auto compute_stage = [&](int s) {
        uint32_t sbase = smb + 2u * (s * 4 * MATA);
        #pragma unroll
        for (int ks = 0; ks < 2; ks++) {
            uint32_t abase = sbase + a_off + 2u * (ks * 16);
            uint32_t bbase = sbase + 2u * (2 * MATA) + b_off + 2u * (ks * 16);
            uint32_t fah[16], fbh[8], flo[16];
            #pragma unroll
            for (int mt = 0; mt < 4; mt++) LDSM4(&fah[mt * 4], abase + 2u * (mt * 16 * SROW));
            #pragma unroll
            for (int p = 0; p < 2; p++)  LDSM4(&fbh[p * 4], bbase + 2u * (p * 16 * SROW));
            #pragma unroll
            for (int mt = 0; mt < 4; mt++)
                #pragma unroll
                for (int nt = 0; nt < 4; nt++)
                    mma16816(acc[mt][nt], &fah[mt * 4], &fbh[(nt >> 1) * 4 + (nt & 1) * 2]);
            #pragma unroll
            for (int mt = 0; mt < 4; mt++) LDSM4(&flo[mt * 4], abase + 2u * MATA + 2u * (mt * 16 * SROW));
            #pragma unroll
            for (int mt = 0; mt < 4; mt++)
                #pragma unroll
                for (int nt = 0; nt < 4; nt++)
                    mma16816(acc[mt][nt], &flo[mt * 4], &fbh[(nt >> 1) * 4 + (nt & 1) * 2]);
            #pragma unroll
            for (int p = 0; p < 2; p++)  LDSM4(&flo[p * 4], bbase + 2u * MATA + 2u * (p * 16 * SROW));
            #pragma unroll
            for (int mt = 0; mt < 4; mt++)
                #pragma unroll
                for (int nt = 0; nt < 4; nt++)
                    mma16816(acc[mt][nt], &fah[mt * 4], &flo[(nt >> 1) * 4 + (nt & 1) * 2]);
        }
    };

    load_stage(0, 0);
    for (int kt = 0; kt < KT; kt++) {
        int s = kt & 1;
        if (kt + 1 < KT) { load_stage(kt + 1, s ^ 1); CPA_WAIT(1); }
        else             { CPA_WAIT(0); }
        __syncthreads();
        compute_stage(s);
        __syncthreads();
    }

    #pragma unroll
    for (int mt = 0; mt < 4; mt++) {
        #pragma unroll
        for (int nt = 0; nt < 4; nt++) {
            int r = m0 + wm + mt * 16 + g;
            int c = n0 + wn + nt * 8 + 2 * tig;
            if (c < N) {
                float* p0 = C + (size_t)r * ldc + c;
                float* p1 = C + (size_t)(r + 8) * ldc + c;
                p0[0] = acc[mt][nt][0]; p1[0] = acc[mt][nt][2];
                if (c + 1 < N) { p0[1] = acc[mt][nt][1]; p1[1] = acc[mt][nt][3]; }
            }
        }
    }
}

// ================= reduces =================
__global__ void xreduce_kernel(const float* __restrict__ xp, float* __restrict__ xdbl,
                               __nv_bfloat16* __restrict__ xdh, __nv_bfloat16* __restrict__ xdl) {
    int i = blockIdx.x * blockDim.x + threadIdx.x;
    if (i >= BL * XDW) return;
    float s = 0.f;
    #pragma unroll
    for (int z = 0; z < 8; z++) s += xp[(size_t)z * BL * XDW + i];
    xdbl[i] = s;
    int c = i % XDW, r = i / XDW;
    if (c < 64) {
        __nv_bfloat16 h = __float2bfloat16_rn(s);
        xdh[(size_t)r * 64 + c] = h;
        xdl[(size_t)r * 64 + c] = __float2bfloat16_rn(s - __bfloat162float(h));
    }
}
__global__ void oreduce_kernel(const float* __restrict__ p, float* __restrict__ x) {
    int i = blockIdx.x * blockDim.x + threadIdx.x;
    if (i >= BL * DM) return;
    x[i] += p[i] + p[(size_t)BL * DM + i] + p[(size_t)2 * BL * DM + i];
}

// ================= elementwise =================
__global__ void embed_kernel(const int* __restrict__ ids, const float* __restrict__ emb,
                             float* __restrict__ x) {
    int i = blockIdx.x * blockDim.x + threadIdx.x;
    if (i >= BL * DM) return;
    int r = i / DM, c = i % DM;
    x[i] = emb[(size_t)ids[r] * DM + c];
}

__global__ __launch_bounds__(256) void rmsnorm_split_kernel(const float* __restrict__ x,
                                                            const float* __restrict__ w,
                                                            __nv_bfloat16* __restrict__ oh,
                                                            __nv_bfloat16* __restrict__ ol) {
    int row = blockIdx.x;
    const float* xrow = x + (size_t)row * DM;
    float s = 0.f;
    for (int c = threadIdx.x; c < DM; c += 256) { float v = xrow[c]; s = fmaf(v, v, s); }
    #pragma unroll
    for (int off = 16; off; off >>= 1) s += __shfl_xor_sync(0xffffffffu, s, off);
    __shared__ float red[8];
    if ((threadIdx.x & 31) == 0) red[threadIdx.x >> 5] = s;
    __syncthreads();
    float tot = red[0] + red[1] + red[2] + red[3] + red[4] + red[5] + red[6] + red[7];
    float sc = rsqrtf(tot * (1.0f / DM) + 1e-5f);
    for (int c = threadIdx.x; c < DM; c += 256) {
        float v = xrow[c] * sc * w[c];
        __nv_bfloat16 h = __float2bfloat16_rn(v);
        oh[(size_t)row * DM + c] = h;
        ol[(size_t)row * DM + c] = __float2bfloat16_rn(v - __bfloat162float(h));
    }
}

__global__ void conv_silu_split_kernel(const float* __restrict__ xr, const float* __restrict__ cw,
                                       const float* __restrict__ cb, float* __restrict__ xin,
                                       __nv_bfloat16* __restrict__ xih, __nv_bfloat16* __restrict__ xil) {
    int i = blockIdx.x * blockDim.x + threadIdx.x;
    if (i >= BL * DI) return;
    int d = i % DI;
    int bl = i / DI;
    int l = bl % LL;
    float w0 = cw[d * 4], w1 = cw[d * 4 + 1], w2 = cw[d * 4 + 2], w3 = cw[d * 4 + 3];
    const float* base = xr + (size_t)bl * (2 * DI) + d;
    float acc = cb[d];
    if (l >= 3) acc = fmaf(w0, base[-3 * (2 * DI)], acc);
    if (l >= 2) acc = fmaf(w1, base[-2 * (2 * DI)], acc);
    if (l >= 1) acc = fmaf(w2, base[-1 * (2 * DI)], acc);
    acc = fmaf(w3, base[0], acc);
    float v = acc / (1.f + expf(-acc));
    xin[i] = v;
    __nv_bfloat16 h = __float2bfloat16_rn(v);
    xih[i] = h;
    xil[i] = __float2bfloat16_rn(v - __bfloat162float(h));
}

// ---------------- selective scan + fused gate + bf16 split ----------------
__global__ __launch_bounds__(128) void scan_gate_kernel(const float* __restrict__ u,
                                                        const float* __restrict__ delta,
                                                        const float* __restrict__ xdbl,
                                                        const float* __restrict__ A_log,
                                                        const float* __restrict__ Dp,
                                                        const float* __restrict__ xr,
                                                        __nv_bfloat16* __restrict__ yh,
                                                        __nv_bfloat16* __restrict__ yl) {
    int tid = blockIdx.x * blockDim.x + threadIdx.x;
    if (tid >= BB * DI * 2) return;
    int half = tid & 1;
    int pair = tid >> 1;
    int d = pair % DI;
    int b = pair / DI;

    float A[8];
    float A0 = -expf(A_log[d * DS]);
    bool structured = true;
    #pragma unroll
    for (int n = 0; n < 8; n++) {
        int ng = half * 8 + n;
        A[n] = -expf(A_log[d * DS + ng]);
        float e = (float)(ng + 1) * A0;
        if (fabsf(A[n] - e) > 1e-3f * fabsf(e)) structured = false;
    }
    float Dd = Dp[d];
    float h[8];
    #pragma unroll
    for (int n = 0; n < 8; n++) h[n] = 0.f;

    const float* up = u + (size_t)b * LL * DI + d;
    const float* dp = delta + (size_t)b * LL * DI + d;
    const float* xp = xdbl + (size_t)b * LL * XDW + DTR + half * 8;
    const float* rp = xr + (size_t)b * LL * (2 * DI) + DI + d;
    size_t ybase = (size_t)b * LL * DI + d;

    float del = dp[0], uu = up[0], rr = rp[0];
    float4 B0 = *(const float4*)(xp);
    float4 B1 = *(const float4*)(xp + 4);
    float4 C0 = *(const float4*)(xp + 16);
    float4 C1 = *(const float4*)(xp + 20);

    for (int l = 0; l < LL; ++l) {
        float ndel = 0.f, nuu = 0.f, nrr = 0.f;
        float4 nB0 = B0, nB1 = B1, nC0 = C0, nC1 = C1;
        if (l + 1 < LL) {
            ndel = dp[(size_t)(l + 1) * DI];
            nuu  = up[(size_t)(l + 1) * DI];
            nrr  = rp[(size_t)(l + 1) * (2 * DI)];
            const float* nx = xp + (size_t)(l + 1) * XDW;
            nB0 = *(const float4*)(nx);
            nB1 = *(const float4*)(nx + 4);
            nC0 = *(const float4*)(nx + 16);
            nC1 = *(const float4*)(nx + 20);
        }
        float Ba[8] = {B0.x, B0.y, B0.z, B0.w, B1.x, B1.y, B1.z, B1.w};
        float Ca[8] = {C0.x, C0.y, C0.z, C0.w, C1.x, C1.y, C1.z, C1.w};
        float dbu = del * uu;
        float ys = 0.f;
        if (structured) {
            float t = __expf(A0 * del);
            float p;
            if (half == 0) p = t;
            else { float t2 = t * t, t4 = t2 * t2, t8 = t4 * t4; p = t8 * t; }
            #pragma unroll
            for (int n = 0; n < 8; n++) {
                h[n] = fmaf(p, h[n], dbu * Ba[n]);
                ys = fmaf(h[n], Ca[n], ys);
                p *= t;
            }
        } else {
            #pragma unroll
            for (int n = 0; n < 8; n++) {
                float dA = __expf(A[n] * del);
                h[n] = fmaf(dA, h[n], dbu * Ba[n]);
                ys = fmaf(h[n], Ca[n], ys);
            }
        }
        ys += __shfl_xor_sync(0xffffffffu, ys, 1);
        if (half == 0) {
            float yv = fmaf(uu, Dd, ys);
            yv *= rr / (1.f + expf(-rr));           // gate
            __nv_bfloat16 hv = __float2bfloat16_rn(yv);
            yh[ybase + (size_t)l * DI] = hv;
            yl[ybase + (size_t)l * DI] = __float2bfloat16_rn(yv - __bfloat162float(hv));
        }
        del = ndel; uu = nuu; rr = nrr;
        B0 = nB0; B1 = nB1; C0 = nC0; C1 = nC1;
    }
}

// ================= host =================
static inline void launch_split(const float* src, int lda, int M, int K,
                                __nv_bfloat16* dhi, __nv_bfloat16* dlo, int Mp, int Kp) {
    int tot = Mp * (Kp / 8);
    split_kernel<<<(tot + 255) / 256, 256>>>(src, lda, M, K, dhi, dlo, Mp, Kp);
}

extern "C" void kernel_launch(void* const* d_in, const int* in_sizes, int n_in,
                              void* d_out, int out_size) {
    const int*   ids       = (const int*)  d_in[0];
    const float* emb       = (const float*)d_in[4];
    const float* norm_w    = (const float*)d_in[5];
    const float* in_proj_w = (const float*)d_in[6];
    const float* conv_w    = (const float*)d_in[7];
    const float* conv_b    = (const float*)d_in[8];
    const float* x_proj_w  = (const float*)d_in[9];
    const float* dt_proj_w = (const float*)d_in[10];
    const float* dt_proj_b = (const float*)d_in[11];
    const float* A_log     = (const float*)d_in[12];
    const float* D_param   = (const float*)d_in[13];
    const float* out_proj_w= (const float*)d_in[14];
    const float* norm_f_w  = (const float*)d_in[15];
    float* out = (float*)d_out;

    float *x, *xr, *xin, *xdbl, *delta, *xp, *op;
    cudaGetSymbolAddress((void**)&x,     g_x);
    cudaGetSymbolAddress((void**)&xr,    g_xr);
    cudaGetSymbolAddress((void**)&xin,   g_xin);
    cudaGetSymbolAddress((void**)&xdbl,  g_xdbl);
    cudaGetSymbolAddress((void**)&delta, g_delta);
    cudaGetSymbolAddress((void**)&xp,    g_xp);
    cudaGetSymbolAddress((void**)&op,    g_op);

    __nv_bfloat16 *Emb_h, *Emb_l, *Win_h, *Win_l, *Wout_h, *Wout_l;
    __nv_bfloat16 *Wx_h, *Wx_l, *Wdt_h, *Wdt_l;
    __nv_bfloat16 *Xn_h, *Xn_l, *Xin_h, *Xin_l, *Xd_h, *Xd_l, *Y_h, *Y_l;
    cudaGetSymbolAddress((void**)&Emb_h,  g_Emb_h);  cudaGetSymbolAddress((void**)&Emb_l,  g_Emb_l);
    cudaGetSymbolAddress((void**)&Win_h,  g_Win_h);  cudaGetSymbolAddress((void**)&Win_l,  g_Win_l);
    cudaGetSymbolAddress((void**)&Wout_h, g_Wout_h); cudaGetSymbolAddress((void**)&Wout_l, g_Wout_l);
    cudaGetSymbolAddress((void**)&Wx_h,   g_Wx_h);   cudaGetSymbolAddress((void**)&Wx_l,   g_Wx_l);
    cudaGetSymbolAddress((void**)&Wdt_h,  g_Wdt_h);  cudaGetSymbolAddress((void**)&Wdt_l,  g_Wdt_l);
    cudaGetSymbolAddress((void**)&Xn_h,   g_Xn_h);   cudaGetSymbolAddress((void**)&Xn_l,   g_Xn_l);
    cudaGetSymbolAddress((void**)&Xin_h,  g_Xin_h);  cudaGetSymbolAddress((void**)&Xin_l,  g_Xin_l);
    cudaGetSymbolAddress((void**)&Xd_h,   g_Xd_h);   cudaGetSymbolAddress((void**)&Xd_l,   g_Xd_l);
    cudaGetSymbolAddress((void**)&Y_h,    g_Y_h);    cudaGetSymbolAddress((void**)&Y_l,    g_Y_l);

    const int SMEM256 = 2 * STG_E * 2;        // 122880 bytes
    const int SMEM128 = 2 * 4 * MATA * 2;     // 81920 bytes
    cudaFuncSetAttribute(gemm256<0>, cudaFuncAttributeMaxDynamicSharedMemorySize, SMEM256);
    cudaFuncSetAttribute(gemm256<2>, cudaFuncAttributeMaxDynamicSharedMemorySize, SMEM256);
    cudaFuncSetAttribute(gemm128,    cudaFuncAttributeMaxDynamicSharedMemorySize, SMEM128);

    // one-time weight/emb splits
    for (int L = 0; L < NL; ++L) {
        launch_split(in_proj_w + (size_t)L * 2 * DI * DM, DM, 2 * DI, DM,
                     Win_h + (size_t)L * 2 * DI * DM, Win_l + (size_t)L * 2 * DI * DM, 2 * DI, DM);
        launch_split(out_proj_w + (size_t)L * DM * DI, DI, DM, DI,
                     Wout_h + (size_t)L * DM * DI, Wout_l + (size_t)L * DM * DI, DM, DI);
        launch_split(x_proj_w + (size_t)L * XDW * DI, DI, XDW, DI,
                     Wx_h + (size_t)L * 128 * DI, Wx_l + (size_t)L * 128 * DI, 128, DI);
        launch_split(dt_proj_w + (size_t)L * DI * DTR, DTR, DI, DTR,
                     Wdt_h + (size_t)L * DI * 64, Wdt_l + (size_t)L * DI * 64, DI, 64);
    }
    launch_split(emb, DM, VOC, DM, Emb_h, Emb_l, VOC, DM);

    embed_kernel<<<(BL * DM + 255) / 256, 256>>>(ids, emb, x);

    for (int L = 0; L < NL; ++L) {
        rmsnorm_split_kernel<<<BL, 256>>>(x, norm_w + (size_t)L * DM, Xn_h, Xn_l);

        // in_proj: (2048x768) @ (3072x768)^T -> xr
        gemm256<0><<<dim3(12, 16), 256, SMEM256>>>(
            Xn_h, Xn_l, Win_h + (size_t)L * 2 * DI * DM, Win_l + (size_t)L * 2 * DI * DM,
            xr, 2 * DI, DM, 24, 0, nullptr);

        conv_silu_split_kernel<<<(BL * DI + 255) / 256, 256>>>(
            xr, conv_w + (size_t)L * DI * 4, conv_b + (size_t)L * DI, xin, Xin_h, Xin_l);

        // x_proj split-K=8: (2048x1536) @ (80x1536)^T -> 8 partials
        gemm128<<<dim3(1, 16, 8), 256, SMEM128>>>(
            Xin_h, Xin_l, Wx_h + (size_t)L * 128 * DI, Wx_l + (size_t)L * 128 * DI,
            xp, XDW, XDW, DI, 6, (size_t)BL * XDW);
        xreduce_kernel<<<(BL * XDW + 255) / 256, 256>>>(xp, xdbl, Xd_h, Xd_l);

        // dt_proj + softplus(.. + bias): (2048x64) @ (1536x64)^T -> delta
        gemm256<2><<<dim3(6, 16), 256, SMEM256>>>(
            Xd_h, Xd_l, Wdt_h + (size_t)L * DI * 64, Wdt_l + (size_t)L * DI * 64,
            delta, DI, 64, 2, 0, dt_proj_b + (size_t)L * DI);

        scan_gate_kernel<<<(BB * DI * 2) / 128, 128>>>(
            xin, delta, xdbl, A_log + (size_t)L * DI * DS, D_param + (size_t)L * DI,
            xr, Y_h, Y_l);

        // out_proj split-K=3: (2048x1536) @ (768x1536)^T -> 3 partials; reduce-add into x
        gemm256<0><<<dim3(3, 16, 3), 256, SMEM256>>>(
            Y_h, Y_l, Wout_h + (size_t)L * DM * DI, Wout_l + (size_t)L * DM * DI,
            op, DM, DI, 16, (size_t)BL * DM, nullptr);
        oreduce_kernel<<<(BL * DM + 255) / 256, 256>>>(op, x);
    }

    rmsnorm_split_kernel<<<BL, 256>>>(x, norm_f_w, Xn_h, Xn_l);

    // lm_head: (2048x768) @ (32000x768)^T -> out
    gemm256<0><<<dim3(125, 16), 256, SMEM256>>>(
        Xn_h, Xn_l, Emb_h, Emb_l, out, VOC, DM, 24, 0, nullptr);
}